// round 12
// baseline (speedup 1.0000x reference)
#include <cuda_runtime.h>
#include <cuda_fp16.h>
#include <cstdint>

#define E_ 8
#define T_ 16384
#define D_ 2048
#define H_ 1024

// ---------------- scratch: fp16 operands, plain row-major ---------------------
__device__ __align__(1024) __half g_x [T_ * (size_t)D_];
__device__ __align__(1024) __half g_w1[E_ * (size_t)H_ * D_];
__device__ __align__(1024) __half g_w3[E_ * (size_t)H_ * D_];
__device__ __align__(1024) __half g_w2[E_ * (size_t)D_ * H_];
__device__ __align__(1024) __half g_h [T_ * (size_t)H_];

// ---------------- dependency counters (reset per call) ------------------------
__device__ int g_xflag[128];    // one per 128-token chunk of x
__device__ int g_w13cnt[8];     // per expert, target 16

// ---------------- helpers ----------------
__device__ __forceinline__ uint32_t smem_u32(const void* p) {
    uint32_t a;
    asm("{ .reg .u64 t; cvta.to.shared.u64 t, %1; cvt.u32.u64 %0, t; }" : "=r"(a) : "l"(p));
    return a;
}
__device__ __forceinline__ uint32_t f22h(float lo, float hi) {   // fp16x2 {lo,hi}
    uint32_t r;
    asm("cvt.rn.f16x2.f32 %0, %1, %2;" : "=r"(r) : "f"(hi), "f"(lo));
    return r;
}
__device__ __forceinline__ void cp16(__half* sdst, const __half* gsrc) {
    uint32_t s = smem_u32(sdst);
    asm volatile("cp.async.cg.shared.global [%0], [%1], 16;" :: "r"(s), "l"(gsrc) : "memory");
}
__device__ __forceinline__ void ldm_x4(uint32_t& r0, uint32_t& r1, uint32_t& r2, uint32_t& r3,
                                       uint32_t addr) {
    asm volatile("ldmatrix.sync.aligned.m8n8.x4.shared.b16 {%0,%1,%2,%3}, [%4];"
                 : "=r"(r0), "=r"(r1), "=r"(r2), "=r"(r3) : "r"(addr));
}
__device__ __forceinline__ void mma_f16(float* c, const uint32_t* a, const uint32_t* b) {
    asm volatile(
        "mma.sync.aligned.m16n8k16.row.col.f32.f16.f16.f32 "
        "{%0,%1,%2,%3}, {%4,%5,%6,%7}, {%8,%9}, {%0,%1,%2,%3};"
        : "+f"(c[0]), "+f"(c[1]), "+f"(c[2]), "+f"(c[3])
        : "r"(a[0]), "r"(a[1]), "r"(a[2]), "r"(a[3]), "r"(b[0]), "r"(b[1]));
}
__device__ __forceinline__ float silu(float a) { return a / (1.f + __expf(-a)); }

#define STG_BYTES 32768
#define NSTG 3
#define SMEM_SZ (NSTG * STG_BYTES)   // 96 KB -> 2 CTAs/SM

__device__ __forceinline__ void pack8(const float4* __restrict__ src,
                                      __half* __restrict__ dst, size_t u) {
    float4 v0 = src[u * 2], v1 = src[u * 2 + 1];
    uint4 o;
    o.x = f22h(v0.x, v0.y);
    o.y = f22h(v0.z, v0.w);
    o.z = f22h(v1.x, v1.y);
    o.w = f22h(v1.z, v1.w);
    ((uint4*)dst)[u] = o;
}

__global__ void init_cnt() {
    int i = threadIdx.x;
    if (i < 8) g_w13cnt[i] = 0;
    if (i < 128) g_xflag[i] = 0;
}

// ---------------- GEMM1 with fully fused pack ----------------------------------
// grid 2368: bids [0,320) pack (x:128, w13:128 interleaved; w2:64), [320,2368) GEMM tiles.
// GEMM: CTA 128M x 64N (each of w1,w3), BK=64; 256 thr, 8 warps (2m x 4n).
__global__ void __launch_bounds__(256, 2) moe_gemm1(
    const float4* __restrict__ xin, const float4* __restrict__ w1in,
    const float4* __restrict__ w3in, const float4* __restrict__ w2in) {
    extern __shared__ __half sm[];
    const uint32_t sb = smem_u32(sm);
    const int tid = threadIdx.x, lane = tid & 31, wid = tid >> 5;
    const int g = lane >> 2, t = lane & 3, s7 = lane & 7;
    const int bxr = blockIdx.x;

    if (bxr < 320) {                                // ======== pack blocks ========
        if (bxr < 256) {
            int j = bxr >> 1;
            if ((bxr & 1) == 0) {
                // x chunk j: 32768 units of 8 floats (128 token rows)
                size_t base = (size_t)j * 32768;
                #pragma unroll 4
                for (int k = 0; k < 128; ++k) pack8(xin, g_x, base + tid + 256 * (size_t)k);
                __threadfence();
                __syncthreads();
                if (tid == 0) atomicExch(&g_xflag[j], 1);
            } else {
                // w13 block j: expert e, sub-block of 32768 units over w1|w3 concat
                int e = j >> 4, sub = j & 15;
                size_t base = (size_t)sub * 32768;
                #pragma unroll 4
                for (int k = 0; k < 128; ++k) {
                    size_t u = base + tid + 256 * (size_t)k;
                    if (u < 262144) pack8(w1in, g_w1, (size_t)e * 262144 + u);
                    else            pack8(w3in, g_w3, (size_t)e * 262144 + (u - 262144));
                }
                __threadfence();
                __syncthreads();
                if (tid == 0) atomicAdd(&g_w13cnt[e], 1);
            }
        } else {
            // w2: 64 grid-stride blocks over 2097152 units (done before kernel end)
            size_t pid = (size_t)(bxr - 256);
            for (size_t i = pid * 256 + tid; i < 2097152; i += 64 * 256)
                pack8(w2in, g_w2, i);
        }
        return;
    }

    const int bx = bxr - 320;                       // ======== GEMM1 tile ========
    const int e = bx >> 8, mt = (bx >> 4) & 15, nt = bx & 15;
    const int mtg = bx >> 4;                        // token chunk 0..127
    const int m0 = e * 2048 + mt * 128, n0 = nt * 64;

    if (tid == 0) {
        while (atomicAdd(&g_w13cnt[e], 0) < 16) __nanosleep(128);
        while (atomicAdd(&g_xflag[mtg], 0) == 0) __nanosleep(128);
    }
    __syncthreads();

    const __half* A  = g_x  + (size_t)m0 * D_;
    const __half* B1 = g_w1 + (size_t)(e * H_ + n0) * D_;
    const __half* B3 = g_w3 + (size_t)(e * H_ + n0) * D_;
    const int KIT = D_ / 64;  // 32
    const int m_off = (wid & 1) * 64, n_off = (wid >> 1) * 16;

    uint32_t aA[4], bA[4];
    #pragma unroll
    for (int kk = 0; kk < 4; ++kk) {
        aA[kk] = sb + (uint32_t)(m_off + (lane & 15)) * 128u
                    + 16u * ((((lane >> 4) | (kk << 1)) ^ s7));
        bA[kk] = sb + 16384u + (uint32_t)(n_off + 8 * (lane >> 4) + s7) * 128u
                    + 16u * (((((lane >> 3) & 1) | (kk << 1)) ^ s7));
    }

    float c1[4][2][4], c3[4][2][4];
    #pragma unroll
    for (int i = 0; i < 4; ++i)
        #pragma unroll
        for (int j = 0; j < 2; ++j)
            #pragma unroll
            for (int q = 0; q < 4; ++q) { c1[i][j][q] = 0.f; c3[i][j][q] = 0.f; }

    auto issue = [&](int s, int kt) {
        __half* dst = sm + (size_t)s * (STG_BYTES / 2);
        const int koff = kt * 64;
        #pragma unroll
        for (int i = 0; i < 4; ++i) {             // A: 128 rows x 8 chunks
            int idx = tid + 256 * i, r = idx >> 3, c = idx & 7;
            cp16(dst + r * 64 + ((c ^ (r & 7)) << 3), A + (size_t)r * D_ + koff + c * 8);
        }
        __half* d1 = dst + 8192;
        __half* d3 = dst + 12288;
        #pragma unroll
        for (int i = 0; i < 2; ++i) {             // B1,B3: 64 rows x 8 chunks
            int idx = tid + 256 * i, r = idx >> 3, c = idx & 7;
            cp16(d1 + r * 64 + ((c ^ (r & 7)) << 3), B1 + (size_t)r * D_ + koff + c * 8);
            cp16(d3 + r * 64 + ((c ^ (r & 7)) << 3), B3 + (size_t)r * D_ + koff + c * 8);
        }
        asm volatile("cp.async.commit_group;" ::: "memory");
    };

    issue(0, 0); issue(1, 1);
    int cs = 0;
    for (int kt = 0; kt < KIT; ++kt) {
        if (kt + 1 < KIT) asm volatile("cp.async.wait_group 1;" ::: "memory");
        else              asm volatile("cp.async.wait_group 0;" ::: "memory");
        __syncthreads();
        if (kt + 2 < KIT) { int ns = cs + 2; if (ns >= 3) ns -= 3; issue(ns, kt + 2); }
        const uint32_t soff = (uint32_t)cs * STG_BYTES;
        #pragma unroll
        for (int kk = 0; kk < 4; ++kk) {
            uint32_t a[4][4], b1f[2][2], b3f[2][2];
            #pragma unroll
            for (int mi = 0; mi < 4; ++mi)
                ldm_x4(a[mi][0], a[mi][1], a[mi][2], a[mi][3],
                       aA[kk] + soff + mi * 2048u);
            ldm_x4(b1f[0][0], b1f[0][1], b1f[1][0], b1f[1][1], bA[kk] + soff);
            ldm_x4(b3f[0][0], b3f[0][1], b3f[1][0], b3f[1][1], bA[kk] + soff + 8192u);
            #pragma unroll
            for (int mi = 0; mi < 4; ++mi)
                #pragma unroll
                for (int nj = 0; nj < 2; ++nj) {
                    mma_f16(c1[mi][nj], a[mi], b1f[nj]);
                    mma_f16(c3[mi][nj], a[mi], b3f[nj]);
                }
        }
        if (++cs == 3) cs = 0;
    }

    // epilogue: h = fp16(silu(c1)*c3), plain row-major
    #pragma unroll
    for (int mi = 0; mi < 4; ++mi)
        #pragma unroll
        for (int nj = 0; nj < 2; ++nj) {
            int r0 = m0 + m_off + 16 * mi + g;
            int col = n0 + n_off + 8 * nj + 2 * t;
            uint32_t v0 = f22h(silu(c1[mi][nj][0]) * c3[mi][nj][0],
                               silu(c1[mi][nj][1]) * c3[mi][nj][1]);
            uint32_t v1 = f22h(silu(c1[mi][nj][2]) * c3[mi][nj][2],
                               silu(c1[mi][nj][3]) * c3[mi][nj][3]);
            *(uint32_t*)(g_h + (size_t)r0 * H_ + col)       = v0;
            *(uint32_t*)(g_h + (size_t)(r0 + 8) * H_ + col) = v1;
        }
}

// ---------------- GEMM2: out = h @ w2^T ---------------------------------------
// CTA 128M x 128N, BK=64, K=1024; 256 thr, 8 warps (2m x 4n), warp 64x32
__global__ void __launch_bounds__(256, 2) moe_gemm2(float* __restrict__ out) {
    extern __shared__ __half sm[];
    const uint32_t sb = smem_u32(sm);
    const int tid = threadIdx.x, lane = tid & 31, wid = tid >> 5;
    const int g = lane >> 2, t = lane & 3, s7 = lane & 7;
    const int bx = blockIdx.x;
    const int e = bx >> 8, mt = (bx >> 4) & 15, nt = bx & 15;
    const int m0 = e * 2048 + mt * 128, n0 = nt * 128;
    const __half* A = g_h  + (size_t)m0 * H_;
    const __half* B = g_w2 + ((size_t)e * D_ + n0) * H_;
    const int KIT = H_ / 64;  // 16
    const int m_off = (wid & 1) * 64, n_off = (wid >> 1) * 32;

    uint32_t aA[4], bA[4];
    #pragma unroll
    for (int kk = 0; kk < 4; ++kk) {
        aA[kk] = sb + (uint32_t)(m_off + (lane & 15)) * 128u
                    + 16u * ((((lane >> 4) | (kk << 1)) ^ s7));
        bA[kk] = sb + 16384u + (uint32_t)(n_off + 8 * (lane >> 4) + s7) * 128u
                    + 16u * (((((lane >> 3) & 1) | (kk << 1)) ^ s7));
    }

    float cc[4][4][4];
    #pragma unroll
    for (int i = 0; i < 4; ++i)
        #pragma unroll
        for (int j = 0; j < 4; ++j)
            #pragma unroll
            for (int q = 0; q < 4; ++q) cc[i][j][q] = 0.f;

    auto issue = [&](int s, int kt) {
        __half* dst = sm + (size_t)s * (STG_BYTES / 2);
        const int koff = kt * 64;
        #pragma unroll
        for (int i = 0; i < 4; ++i) {             // A: 128 x 8 chunks
            int idx = tid + 256 * i, r = idx >> 3, c = idx & 7;
            cp16(dst + r * 64 + ((c ^ (r & 7)) << 3), A + (size_t)r * H_ + koff + c * 8);
        }
        __half* db = dst + 8192;
        #pragma unroll
        for (int i = 0; i < 4; ++i) {             // B: 128 x 8 chunks
            int idx = tid + 256 * i, r = idx >> 3, c = idx & 7;
            cp16(db + r * 64 + ((c ^ (r & 7)) << 3), B + (size_t)r * H_ + koff + c * 8);
        }
        asm volatile("cp.async.commit_group;" ::: "memory");
    };

    issue(0, 0); issue(1, 1);
    int cs = 0;
    for (int kt = 0; kt < KIT; ++kt) {
        if (kt + 1 < KIT) asm volatile("cp.async.wait_group 1;" ::: "memory");
        else              asm volatile("cp.async.wait_group 0;" ::: "memory");
        __syncthreads();
        if (kt + 2 < KIT) { int ns = cs + 2; if (ns >= 3) ns -= 3; issue(ns, kt + 2); }
        const uint32_t soff = (uint32_t)cs * STG_BYTES;
        #pragma unroll
        for (int kk = 0; kk < 4; ++kk) {
            uint32_t a[4][4], bf[4][2];
            #pragma unroll
            for (int mi = 0; mi < 4; ++mi)
                ldm_x4(a[mi][0], a[mi][1], a[mi][2], a[mi][3],
                       aA[kk] + soff + mi * 2048u);
            #pragma unroll
            for (int j = 0; j < 2; ++j)
                ldm_x4(bf[2*j][0], bf[2*j][1], bf[2*j+1][0], bf[2*j+1][1],
                       bA[kk] + soff + j * 2048u);
            #pragma unroll
            for (int mi = 0; mi < 4; ++mi)
                #pragma unroll
                for (int nj = 0; nj < 4; ++nj)
                    mma_f16(cc[mi][nj], a[mi], bf[nj]);
        }
        if (++cs == 3) cs = 0;
    }

    #pragma unroll
    for (int mi = 0; mi < 4; ++mi)
        #pragma unroll
        for (int nj = 0; nj < 4; ++nj) {
            int r0 = m0 + m_off + 16 * mi + g;
            int col = n0 + n_off + 8 * nj + 2 * t;
            float2 v;
            v.x = cc[mi][nj][0]; v.y = cc[mi][nj][1];
            *(float2*)(out + (size_t)r0 * D_ + col) = v;
            v.x = cc[mi][nj][2]; v.y = cc[mi][nj][3];
            *(float2*)(out + (size_t)(r0 + 8) * D_ + col) = v;
        }
}

// ---------------- launch ----------------
extern "C" void kernel_launch(void* const* d_in, const int* in_sizes, int n_in,
                              void* d_out, int out_size) {
    const float4* x  = (const float4*)d_in[0];
    const float4* w1 = (const float4*)d_in[2];
    const float4* w2 = (const float4*)d_in[3];
    const float4* w3 = (const float4*)d_in[4];
    float* out = (float*)d_out;

    init_cnt<<<1, 128>>>();

    cudaFuncSetAttribute(moe_gemm1, cudaFuncAttributeMaxDynamicSharedMemorySize, SMEM_SZ);
    cudaFuncSetAttribute(moe_gemm2, cudaFuncAttributeMaxDynamicSharedMemorySize, SMEM_SZ);

    moe_gemm1<<<2368, 256, SMEM_SZ>>>(x, w1, w3, w2);  // 320 pack + 2048 gemm tiles
    moe_gemm2<<<2048, 256, SMEM_SZ>>>(out);
}